// round 8
// baseline (speedup 1.0000x reference)
#include <cuda_runtime.h>
#include <math.h>
#include <float.h>
#include <stdint.h>

#define BSZ 256
#define DIM 1024
#define SS  32768
#define NT  (SS / 128)   // 256 n-tiles

#define GBM 128
#define GBN 128
#define LDWB 20          // words per smem row: 16 (64 int8) + 4 pad

// -------- device scratch (allocation-free rule) --------
__device__ uint32_t g_xq[(size_t)BSZ * DIM / 4];          // int8 x, packed
__device__ float    g_sx[BSZ];
__device__ uint32_t g_wq[(size_t)SS * DIM / 4];           // int8 gathered w, packed
__device__ float    g_sw[SS];
__device__ float    g_bg[SS];                             // gathered bias
__device__ float    g_pz [(size_t)BSZ * NT];
__device__ float    g_ptl[(size_t)BSZ * NT];
__device__ float    g_pst[(size_t)BSZ * NT];

__device__ __forceinline__ int q8(float v, float inv) {
    int q = __float2int_rn(v * inv);
    return max(-127, min(127, q));
}
__device__ __forceinline__ uint32_t pack4(int a, int b, int c, int d) {
    return (uint32_t)(uint8_t)a | ((uint32_t)(uint8_t)b << 8) |
           ((uint32_t)(uint8_t)c << 16) | ((uint32_t)(uint8_t)d << 24);
}

// ---------------------------------------------------------------------------
// Kernel 0: per-row quantize x -> int8 + scale. One block per batch row.
// ---------------------------------------------------------------------------
__global__ __launch_bounds__(256) void qx_kernel(const float* __restrict__ x)
{
    const int row = blockIdx.x, tid = threadIdx.x;
    float4 v = ((const float4*)x)[row * 256 + tid];
    float m = fmaxf(fmaxf(fabsf(v.x), fabsf(v.y)), fmaxf(fabsf(v.z), fabsf(v.w)));
#pragma unroll
    for (int o = 16; o; o >>= 1) m = fmaxf(m, __shfl_xor_sync(0xffffffffu, m, o));
    __shared__ float wm[8];
    if ((tid & 31) == 0) wm[tid >> 5] = m;
    __syncthreads();
    m = fmaxf(fmaxf(fmaxf(wm[0], wm[1]), fmaxf(wm[2], wm[3])),
              fmaxf(fmaxf(wm[4], wm[5]), fmaxf(wm[6], wm[7])));
    const float s = fmaxf(m, 1e-30f) / 127.0f;
    const float inv = 1.0f / s;
    g_xq[row * 256 + tid] = pack4(q8(v.x, inv), q8(v.y, inv), q8(v.z, inv), q8(v.w, inv));
    if (tid == 0) g_sx[row] = s;
}

// ---------------------------------------------------------------------------
// Kernel 1: gather sampled weight rows, per-row quantize -> int8 + scale;
// gather bias. One block (128 thr) per sampled row.
// ---------------------------------------------------------------------------
__global__ __launch_bounds__(128) void gw_kernel(const float* __restrict__ weight,
                                                 const float* __restrict__ bias,
                                                 const int* __restrict__ sid)
{
    const int s = blockIdx.x, tid = threadIdx.x;
    const int r = __ldg(&sid[s]);
    const float4* wp = (const float4*)(weight + (size_t)r * DIM);
    float4 v0 = wp[tid * 2], v1 = wp[tid * 2 + 1];
    float m = fmaxf(fmaxf(fmaxf(fabsf(v0.x), fabsf(v0.y)), fmaxf(fabsf(v0.z), fabsf(v0.w))),
                    fmaxf(fmaxf(fabsf(v1.x), fabsf(v1.y)), fmaxf(fabsf(v1.z), fabsf(v1.w))));
#pragma unroll
    for (int o = 16; o; o >>= 1) m = fmaxf(m, __shfl_xor_sync(0xffffffffu, m, o));
    __shared__ float wmx[4];
    if ((tid & 31) == 0) wmx[tid >> 5] = m;
    __syncthreads();
    m = fmaxf(fmaxf(wmx[0], wmx[1]), fmaxf(wmx[2], wmx[3]));
    const float sc = fmaxf(m, 1e-30f) / 127.0f;
    const float inv = 1.0f / sc;
    uint2 o;
    o.x = pack4(q8(v0.x, inv), q8(v0.y, inv), q8(v0.z, inv), q8(v0.w, inv));
    o.y = pack4(q8(v1.x, inv), q8(v1.y, inv), q8(v1.z, inv), q8(v1.w, inv));
    ((uint2*)g_wq)[(size_t)s * 128 + tid] = o;
    if (tid == 0) { g_sw[s] = sc; g_bg[s] = bias[r]; }
}

// ---------------------------------------------------------------------------
// Fused int8 tensor-core GEMM + masked-softmax loss partials.
// BM=BN=128, BK=64. 8 warps (2m x 4n), warp tile 64x32.
// mma.m16n8k32.s8.s32, exact int32 accumulation; scales applied in epilogue.
// ---------------------------------------------------------------------------
__device__ __forceinline__ void imma16832(int* d, const uint32_t* a, const uint32_t* b)
{
    asm volatile(
        "mma.sync.aligned.m16n8k32.row.col.s32.s8.s8.s32 "
        "{%0,%1,%2,%3},{%4,%5,%6,%7},{%8,%9},{%0,%1,%2,%3};"
        : "+r"(d[0]), "+r"(d[1]), "+r"(d[2]), "+r"(d[3])
        : "r"(a[0]), "r"(a[1]), "r"(a[2]), "r"(a[3]), "r"(b[0]), "r"(b[1]));
}

__global__ __launch_bounds__(256, 2) void fused_gemm_s8(
    const float* __restrict__ targets, const int* __restrict__ san)
{
    __shared__ uint32_t sA[2][GBM][LDWB];   // 20,480 B
    __shared__ uint32_t sB[2][GBN][LDWB];   // 20,480 B
    __shared__ float ssc[GBN];
    __shared__ float sbias[GBN];

    const int tid  = threadIdx.x;
    const int m0   = blockIdx.x * GBM;
    const int n0   = blockIdx.y * GBN;
    const int bn   = blockIdx.y;
    const int wid  = tid >> 5;
    const int lane = tid & 31;
    const int wm   = (wid & 1) * 64;
    const int wn   = (wid >> 1) * 32;
    const int lr   = lane >> 2;
    const int lc   = lane & 3;

    if (tid < GBN) { ssc[tid] = g_sw[n0 + tid]; sbias[tid] = g_bg[n0 + tid]; }

    // global load roles: 2 threads per row, 32B (2 uint4) each
    const int row_ld = tid >> 1;
    const int h_ld   = tid & 1;
    const uint4* pa = (const uint4*)g_xq + (size_t)(m0 + row_ld) * 64;
    const uint4* pb = (const uint4*)g_wq + (size_t)(n0 + row_ld) * 64;

    int acc[4][4][4];
#pragma unroll
    for (int i = 0; i < 4; i++)
#pragma unroll
        for (int j = 0; j < 4; j++)
#pragma unroll
            for (int c = 0; c < 4; c++) acc[i][j][c] = 0;

    // prologue
    {
        uint4 a0 = pa[h_ld * 2], a1 = pa[h_ld * 2 + 1];
        uint4 b0 = pb[h_ld * 2], b1 = pb[h_ld * 2 + 1];
        *(uint4*)&sA[0][row_ld][h_ld * 8]     = a0;
        *(uint4*)&sA[0][row_ld][h_ld * 8 + 4] = a1;
        *(uint4*)&sB[0][row_ld][h_ld * 8]     = b0;
        *(uint4*)&sB[0][row_ld][h_ld * 8 + 4] = b1;
    }
    __syncthreads();

    const int NIT = DIM / 64;   // 16
    for (int it = 0; it < NIT; it++) {
        const int buf = it & 1;
        uint4 na0, na1, nb0, nb1;
        if (it < NIT - 1) {
            na0 = pa[(it + 1) * 4 + h_ld * 2];
            na1 = pa[(it + 1) * 4 + h_ld * 2 + 1];
            nb0 = pb[(it + 1) * 4 + h_ld * 2];
            nb1 = pb[(it + 1) * 4 + h_ld * 2 + 1];
        }

#pragma unroll
        for (int ks = 0; ks < 2; ks++) {
            const int kb = ks * 8;
            uint32_t af[4][4], bf[4][2];
#pragma unroll
            for (int mi = 0; mi < 4; mi++) {
                const int row = wm + mi * 16 + lr;
                af[mi][0] = sA[buf][row][kb + lc];
                af[mi][1] = sA[buf][row + 8][kb + lc];
                af[mi][2] = sA[buf][row][kb + 4 + lc];
                af[mi][3] = sA[buf][row + 8][kb + 4 + lc];
            }
#pragma unroll
            for (int nj = 0; nj < 4; nj++) {
                const int col = wn + nj * 8 + lr;
                bf[nj][0] = sB[buf][col][kb + lc];
                bf[nj][1] = sB[buf][col][kb + 4 + lc];
            }
#pragma unroll
            for (int mi = 0; mi < 4; mi++)
#pragma unroll
                for (int nj = 0; nj < 4; nj++)
                    imma16832(acc[mi][nj], af[mi], bf[nj]);
        }

        if (it < NIT - 1) {
            const int nb = buf ^ 1;
            *(uint4*)&sA[nb][row_ld][h_ld * 8]     = na0;
            *(uint4*)&sA[nb][row_ld][h_ld * 8 + 4] = na1;
            *(uint4*)&sB[nb][row_ld][h_ld * 8]     = nb0;
            *(uint4*)&sB[nb][row_ld][h_ld * 8 + 4] = nb1;
            __syncthreads();
        }
    }

    // ---------------- fused loss epilogue ----------------
    __syncthreads();
    float* sz  = (float*)sA;
    float* stl = sz + 512;
    float* sst = stl + 512;
    const int g = wid >> 1;

#pragma unroll
    for (int mi = 0; mi < 4; mi++) {
        const int row0 = m0 + wm + mi * 16 + lr;
        const int row1 = row0 + 8;
        const float sx0 = g_sx[row0];
        const float sx1 = g_sx[row1];
        const float* tp0 = targets + (size_t)row0 * SS + n0 + wn + 2 * lc;
        const float* tp1 = targets + (size_t)row1 * SS + n0 + wn + 2 * lc;
        const int*   sp0 = san + (size_t)row0 * SS + n0 + wn + 2 * lc;
        const int*   sp1 = san + (size_t)row1 * SS + n0 + wn + 2 * lc;

        float z0 = 0.f, z1 = 0.f, t0 = 0.f, t1 = 0.f, s0 = 0.f, s1 = 0.f;
#pragma unroll
        for (int nj = 0; nj < 4; nj++) {
            const int ca = wn + nj * 8 + 2 * lc;
            const float w0 = ssc[ca], w1 = ssc[ca + 1];
            const float b0 = sbias[ca], b1 = sbias[ca + 1];
            float2 tv0 = *(const float2*)(tp0 + nj * 8);
            float2 tv1 = *(const float2*)(tp1 + nj * 8);
            int2   sv0 = *(const int2*)(sp0 + nj * 8);
            int2   sv1 = *(const int2*)(sp1 + nj * 8);

            float l00 = fmaf((float)acc[mi][nj][0], sx0 * w0, b0);
            float l01 = fmaf((float)acc[mi][nj][1], sx0 * w1, b1);
            float l10 = fmaf((float)acc[mi][nj][2], sx1 * w0, b0);
            float l11 = fmaf((float)acc[mi][nj][3], sx1 * w1, b1);

            if (sv0.x) z0 += __expf(l00);
            if (sv0.y) z0 += __expf(l01);
            if (sv1.x) z1 += __expf(l10);
            if (sv1.y) z1 += __expf(l11);

            t0 = fmaf(tv0.x, l00, t0); t0 = fmaf(tv0.y, l01, t0);
            t1 = fmaf(tv1.x, l10, t1); t1 = fmaf(tv1.y, l11, t1);
            s0 += tv0.x + tv0.y;
            s1 += tv1.x + tv1.y;
        }
#pragma unroll
        for (int o = 1; o <= 2; o <<= 1) {
            z0 += __shfl_xor_sync(0xffffffffu, z0, o);
            z1 += __shfl_xor_sync(0xffffffffu, z1, o);
            t0 += __shfl_xor_sync(0xffffffffu, t0, o);
            t1 += __shfl_xor_sync(0xffffffffu, t1, o);
            s0 += __shfl_xor_sync(0xffffffffu, s0, o);
            s1 += __shfl_xor_sync(0xffffffffu, s1, o);
        }
        if (lc == 0) {
            const int r0l = wm + mi * 16 + lr;
            sz [g * 128 + r0l]     = z0;
            sz [g * 128 + r0l + 8] = z1;
            stl[g * 128 + r0l]     = t0;
            stl[g * 128 + r0l + 8] = t1;
            sst[g * 128 + r0l]     = s0;
            sst[g * 128 + r0l + 8] = s1;
        }
    }
    __syncthreads();

    if (tid < GBM) {
        const size_t o = (size_t)(m0 + tid) * NT + bn;
        g_pz [o] = sz [tid] + sz [128 + tid] + sz [256 + tid] + sz [384 + tid];
        g_ptl[o] = stl[tid] + stl[128 + tid] + stl[256 + tid] + stl[384 + tid];
        g_pst[o] = sst[tid] + sst[128 + tid] + sst[256 + tid] + sst[384 + tid];
    }
}

// ---------------------------------------------------------------------------
// Loss + mean in one block: 1024 threads, 4 per batch row.
// ---------------------------------------------------------------------------
__global__ __launch_bounds__(1024) void loss_final_kernel(float* __restrict__ out)
{
    const int t = threadIdx.x;
    const int row = t >> 2, q = t & 3;
    const float* pz  = g_pz  + (size_t)row * NT + q * 64;
    const float* ptl = g_ptl + (size_t)row * NT + q * 64;
    const float* pst = g_pst + (size_t)row * NT + q * 64;
    float z = 0.f, tl = 0.f, st = 0.f;
#pragma unroll 8
    for (int j = 0; j < 64; j++) { z += pz[j]; tl += ptl[j]; st += pst[j]; }
#pragma unroll
    for (int o = 1; o <= 2; o <<= 1) {
        z  += __shfl_xor_sync(0xffffffffu, z, o);
        tl += __shfl_xor_sync(0xffffffffu, tl, o);
        st += __shfl_xor_sync(0xffffffffu, st, o);
    }
    __shared__ float sl[256];
    if (q == 0) sl[row] = logf(z) * st - tl;
    __syncthreads();
    for (int off = 128; off; off >>= 1) {
        if (t < off) sl[t] += sl[t + off];
        __syncthreads();
    }
    if (t == 0) out[0] = sl[0] / (float)BSZ;
}

extern "C" void kernel_launch(void* const* d_in, const int* in_sizes, int n_in,
                              void* d_out, int out_size)
{
    const float* x       = (const float*)d_in[0];
    const float* weight  = (const float*)d_in[1];
    const float* bias    = (const float*)d_in[2];
    const float* targets = (const float*)d_in[3];
    const int*   sid     = (const int*)d_in[4];
    const int*   san     = (const int*)d_in[5];

    qx_kernel<<<BSZ, 256>>>(x);
    gw_kernel<<<SS, 128>>>(weight, bias, sid);
    dim3 gg(BSZ / GBM, SS / GBN);   // (2, 256); m fast -> gathered int8 reused via L2
    fused_gemm_s8<<<gg, 256>>>(targets, san);
    loss_final_kernel<<<1, 1024>>>((float*)d_out);
}

// round 9
// speedup vs baseline: 1.4557x; 1.4557x over previous
#include <cuda_runtime.h>
#include <cuda_bf16.h>
#include <math.h>
#include <float.h>
#include <stdint.h>

#define BSZ 256
#define DIM 1024
#define SS  32768
#define NT  (SS / 128)

#define GBM 128
#define GBN 128
#define LDW 20     // words per smem row: 16 (32 bf16) + 4 pad (80 B pitch)

// -------- device scratch (allocation-free rule) --------
__device__ __align__(16) __nv_bfloat16 g_xbf[(size_t)BSZ * DIM];  // 0.5 MB
__device__ float g_pz [(size_t)BSZ * NT];
__device__ float g_ptl[(size_t)BSZ * NT];
__device__ float g_pst[(size_t)BSZ * NT];
__device__ float g_row[BSZ];

// ---------------------------------------------------------------------------
__global__ void convert_x_kernel(const float* __restrict__ x)
{
    int i = blockIdx.x * blockDim.x + threadIdx.x;
    float4 v = ((const float4*)x)[i];
    __nv_bfloat162 p0 = __floats2bfloat162_rn(v.x, v.y);
    __nv_bfloat162 p1 = __floats2bfloat162_rn(v.z, v.w);
    uint2 o;
    o.x = *(const unsigned int*)&p0;
    o.y = *(const unsigned int*)&p1;
    ((uint2*)g_xbf)[i] = o;
}

__device__ __forceinline__ void mma16816(float* d, const uint32_t* a, const uint32_t* b)
{
    asm volatile(
        "mma.sync.aligned.m16n8k16.row.col.f32.bf16.bf16.f32 "
        "{%0,%1,%2,%3},{%4,%5,%6,%7},{%8,%9},{%0,%1,%2,%3};"
        : "+f"(d[0]), "+f"(d[1]), "+f"(d[2]), "+f"(d[3])
        : "r"(a[0]), "r"(a[1]), "r"(a[2]), "r"(a[3]), "r"(b[0]), "r"(b[1]));
}

#define LDSM_X4(r0, r1, r2, r3, a) \
    asm volatile("ldmatrix.sync.aligned.m8n8.x4.shared.b16 {%0,%1,%2,%3}, [%4];" \
        : "=r"(r0), "=r"(r1), "=r"(r2), "=r"(r3) : "r"(a))

__device__ __forceinline__ uint32_t smem_u32(const void* p) {
    uint32_t a;
    asm("{ .reg .u64 t; cvta.to.shared.u64 t, %1; cvt.u32.u64 %0, t; }" : "=r"(a) : "l"(p));
    return a;
}

__device__ __forceinline__ uint4 cvt2bf16(float4 f0, float4 f1)
{
    __nv_bfloat162 a = __floats2bfloat162_rn(f0.x, f0.y);
    __nv_bfloat162 b = __floats2bfloat162_rn(f0.z, f0.w);
    __nv_bfloat162 c = __floats2bfloat162_rn(f1.x, f1.y);
    __nv_bfloat162 d = __floats2bfloat162_rn(f1.z, f1.w);
    uint4 o;
    o.x = *(const unsigned int*)&a;
    o.y = *(const unsigned int*)&b;
    o.z = *(const unsigned int*)&c;
    o.w = *(const unsigned int*)&d;
    return o;
}

// ---------------------------------------------------------------------------
// Fused kernel: gathered bf16 tensor-core GEMM + bias + masked-softmax loss
// partials. grid = (2, 256), 256 threads (8 warps, 2m x 4n), warp tile 64x32.
// Fragment loads via ldmatrix.x4 (conflict-free at 80 B pitch).
// ---------------------------------------------------------------------------
__global__ __launch_bounds__(256, 2) void fused_gemm_kernel(
    const float* __restrict__ weight, const float* __restrict__ bias,
    const int* __restrict__ sid,
    const float* __restrict__ targets, const int* __restrict__ san)
{
    __shared__ uint32_t sA[2][GBM][LDW];   // 20,480 B
    __shared__ uint32_t sB[2][GBN][LDW];   // 20,480 B
    __shared__ float sbias[GBN];
    __shared__ int   srid[GBN];

    const int tid  = threadIdx.x;
    const int m0   = blockIdx.x * GBM;
    const int n0   = blockIdx.y * GBN;
    const int bn   = blockIdx.y;
    const int wid  = tid >> 5;
    const int lane = tid & 31;
    const int wm   = (wid & 1) * 64;
    const int wn   = (wid >> 1) * 32;
    const int lr   = lane >> 2;
    const int lc   = lane & 3;

    if (tid < GBN) {
        int r = __ldg(&sid[n0 + tid]);
        srid[tid] = r;
        sbias[tid] = bias[r];
    }
    __syncthreads();

    // global load roles: 2 threads per row
    const int row_ld = tid >> 1;
    const int h_ld   = tid & 1;
    const uint4*  pA = (const uint4*)(g_xbf + (size_t)(m0 + row_ld) * DIM);
    const float4* pB = (const float4*)(weight + (size_t)srid[row_ld] * DIM);

    // ldmatrix per-lane base addresses (buf 0, mi/njp 0, kk 0)
    const uint32_t sA_base = smem_u32(sA);
    const uint32_t sB_base = smem_u32(sB);
    const int t8  = (lane & 7) + ((lane >> 3) & 1) * 8;   // row within 16-row tile
    const int kw  = ((lane >> 4) & 1) * 4;                // k-word: 0 or 4
    const uint32_t aAddr0 = sA_base + (((wm + t8) * LDW) + kw) * 4;
    const uint32_t bAddr0 = sB_base + (((wn + t8) * LDW) + kw) * 4;
    const uint32_t BUFA = GBM * LDW * 4;                   // bytes per A stage
    const uint32_t BUFB = GBN * LDW * 4;

    float acc[4][4][4];
#pragma unroll
    for (int i = 0; i < 4; i++)
#pragma unroll
        for (int j = 0; j < 4; j++)
#pragma unroll
            for (int c = 0; c < 4; c++) acc[i][j][c] = 0.f;

    // prologue: stage 0
    {
        uint4 a0 = pA[h_ld * 2 + 0];
        uint4 a1 = pA[h_ld * 2 + 1];
        float4 b0 = pB[h_ld * 4 + 0];
        float4 b1 = pB[h_ld * 4 + 1];
        float4 b2 = pB[h_ld * 4 + 2];
        float4 b3 = pB[h_ld * 4 + 3];
        *(uint4*)&sA[0][row_ld][h_ld * 8 + 0] = a0;
        *(uint4*)&sA[0][row_ld][h_ld * 8 + 4] = a1;
        *(uint4*)&sB[0][row_ld][h_ld * 8 + 0] = cvt2bf16(b0, b1);
        *(uint4*)&sB[0][row_ld][h_ld * 8 + 4] = cvt2bf16(b2, b3);
    }
    __syncthreads();

    const int NIT = DIM / 32;   // 32
    for (int it = 0; it < NIT; it++) {
        const int buf = it & 1;
        const uint32_t aOff = aAddr0 + buf * BUFA;
        const uint32_t bOff = bAddr0 + buf * BUFB;

        uint4 na0, na1, nbu0, nbu1;
        if (it < NIT - 1) {
            const int kq = (it + 1) * 4;
            const int kf = (it + 1) * 8;
            na0 = pA[kq + h_ld * 2 + 0];
            na1 = pA[kq + h_ld * 2 + 1];
            float4 b0 = pB[kf + h_ld * 4 + 0];
            float4 b1 = pB[kf + h_ld * 4 + 1];
            float4 b2 = pB[kf + h_ld * 4 + 2];
            float4 b3 = pB[kf + h_ld * 4 + 3];
            nbu0 = cvt2bf16(b0, b1);
            nbu1 = cvt2bf16(b2, b3);
        }

#pragma unroll
        for (int kk = 0; kk < 2; kk++) {
            uint32_t af[4][4], bfr[4][2];
#pragma unroll
            for (int mi = 0; mi < 4; mi++)
                LDSM_X4(af[mi][0], af[mi][1], af[mi][2], af[mi][3],
                        aOff + (kk * 8) * 4 + mi * (16 * LDW * 4));
            {
                uint32_t r0, r1, r2, r3;
                LDSM_X4(r0, r1, r2, r3, bOff + (kk * 8) * 4);
                bfr[0][0] = r0; bfr[0][1] = r2;
                bfr[1][0] = r1; bfr[1][1] = r3;
                LDSM_X4(r0, r1, r2, r3, bOff + (kk * 8) * 4 + 16 * LDW * 4);
                bfr[2][0] = r0; bfr[2][1] = r2;
                bfr[3][0] = r1; bfr[3][1] = r3;
            }
#pragma unroll
            for (int mi = 0; mi < 4; mi++)
#pragma unroll
                for (int nj = 0; nj < 4; nj++)
                    mma16816(acc[mi][nj], af[mi], bfr[nj]);
        }

        if (it < NIT - 1) {
            const int nb = buf ^ 1;
            *(uint4*)&sA[nb][row_ld][h_ld * 8 + 0] = na0;
            *(uint4*)&sA[nb][row_ld][h_ld * 8 + 4] = na1;
            *(uint4*)&sB[nb][row_ld][h_ld * 8 + 0] = nbu0;
            *(uint4*)&sB[nb][row_ld][h_ld * 8 + 4] = nbu1;
            __syncthreads();
        }
    }

    // ---------------- fused loss epilogue ----------------
    __syncthreads();
    float* sz  = (float*)sA;
    float* stl = sz + 512;
    float* sst = stl + 512;
    const int g = wid >> 1;

#pragma unroll
    for (int mi = 0; mi < 4; mi++) {
        const int row0 = m0 + wm + mi * 16 + lr;
        const int row1 = row0 + 8;
        const float* tp0 = targets + (size_t)row0 * SS + n0 + wn + 2 * lc;
        const float* tp1 = targets + (size_t)row1 * SS + n0 + wn + 2 * lc;
        const int*   sp0 = san + (size_t)row0 * SS + n0 + wn + 2 * lc;
        const int*   sp1 = san + (size_t)row1 * SS + n0 + wn + 2 * lc;

        float z0 = 0.f, z1 = 0.f, t0 = 0.f, t1 = 0.f, s0 = 0.f, s1 = 0.f;
#pragma unroll
        for (int nj = 0; nj < 4; nj++) {
            const float b0 = sbias[wn + nj * 8 + 2 * lc];
            const float b1 = sbias[wn + nj * 8 + 2 * lc + 1];
            float2 tv0 = *(const float2*)(tp0 + nj * 8);
            float2 tv1 = *(const float2*)(tp1 + nj * 8);
            int2   sv0 = *(const int2*)(sp0 + nj * 8);
            int2   sv1 = *(const int2*)(sp1 + nj * 8);

            float l00 = acc[mi][nj][0] + b0;
            float l01 = acc[mi][nj][1] + b1;
            float l10 = acc[mi][nj][2] + b0;
            float l11 = acc[mi][nj][3] + b1;

            if (sv0.x) z0 += __expf(l00);
            if (sv0.y) z0 += __expf(l01);
            if (sv1.x) z1 += __expf(l10);
            if (sv1.y) z1 += __expf(l11);

            t0 = fmaf(tv0.x, l00, t0); t0 = fmaf(tv0.y, l01, t0);
            t1 = fmaf(tv1.x, l10, t1); t1 = fmaf(tv1.y, l11, t1);
            s0 += tv0.x + tv0.y;
            s1 += tv1.x + tv1.y;
        }
#pragma unroll
        for (int o = 1; o <= 2; o <<= 1) {
            z0 += __shfl_xor_sync(0xffffffffu, z0, o);
            z1 += __shfl_xor_sync(0xffffffffu, z1, o);
            t0 += __shfl_xor_sync(0xffffffffu, t0, o);
            t1 += __shfl_xor_sync(0xffffffffu, t1, o);
            s0 += __shfl_xor_sync(0xffffffffu, s0, o);
            s1 += __shfl_xor_sync(0xffffffffu, s1, o);
        }
        if (lc == 0) {
            const int r0l = wm + mi * 16 + lr;
            sz [g * 128 + r0l]     = z0;
            sz [g * 128 + r0l + 8] = z1;
            stl[g * 128 + r0l]     = t0;
            stl[g * 128 + r0l + 8] = t1;
            sst[g * 128 + r0l]     = s0;
            sst[g * 128 + r0l + 8] = s1;
        }
    }
    __syncthreads();

    if (tid < GBM) {
        const size_t o = (size_t)(m0 + tid) * NT + bn;
        g_pz [o] = sz [tid] + sz [128 + tid] + sz [256 + tid] + sz [384 + tid];
        g_ptl[o] = stl[tid] + stl[128 + tid] + stl[256 + tid] + stl[384 + tid];
        g_pst[o] = sst[tid] + sst[128 + tid] + sst[256 + tid] + sst[384 + tid];
    }
}

// ---------------------------------------------------------------------------
// Loss per row: 256 blocks, sum 256 n-tile partials.
// ---------------------------------------------------------------------------
__global__ __launch_bounds__(256) void loss_kernel()
{
    const int b = blockIdx.x;
    const int tid = threadIdx.x;
    float z  = g_pz [b * NT + tid];
    float tl = g_ptl[b * NT + tid];
    float st = g_pst[b * NT + tid];

#pragma unroll
    for (int o = 16; o; o >>= 1) {
        z  += __shfl_xor_sync(0xffffffffu, z, o);
        tl += __shfl_xor_sync(0xffffffffu, tl, o);
        st += __shfl_xor_sync(0xffffffffu, st, o);
    }
    __shared__ float rz[8], rtl[8], rst[8];
    if ((tid & 31) == 0) { rz[tid >> 5] = z; rtl[tid >> 5] = tl; rst[tid >> 5] = st; }
    __syncthreads();
    if (tid < 32) {
        z  = (tid < 8) ? rz[tid]  : 0.f;
        tl = (tid < 8) ? rtl[tid] : 0.f;
        st = (tid < 8) ? rst[tid] : 0.f;
#pragma unroll
        for (int o = 4; o; o >>= 1) {
            z  += __shfl_xor_sync(0xffffffffu, z, o);
            tl += __shfl_xor_sync(0xffffffffu, tl, o);
            st += __shfl_xor_sync(0xffffffffu, st, o);
        }
        if (tid == 0) g_row[b] = logf(z) * st - tl;
    }
}

// ---------------------------------------------------------------------------
__global__ void final_kernel(float* __restrict__ out)
{
    __shared__ float red[256];
    int tid = threadIdx.x;
    red[tid] = g_row[tid];
    __syncthreads();
    for (int off = 128; off; off >>= 1) {
        if (tid < off) red[tid] += red[tid + off];
        __syncthreads();
    }
    if (tid == 0) out[0] = red[0] / (float)BSZ;
}

extern "C" void kernel_launch(void* const* d_in, const int* in_sizes, int n_in,
                              void* d_out, int out_size)
{
    const float* x       = (const float*)d_in[0];
    const float* weight  = (const float*)d_in[1];
    const float* bias    = (const float*)d_in[2];
    const float* targets = (const float*)d_in[3];
    const int*   sid     = (const int*)d_in[4];
    const int*   san     = (const int*)d_in[5];

    convert_x_kernel<<<(BSZ * DIM / 4) / 256, 256>>>(x);
    dim3 gg(BSZ / GBM, SS / GBN);   // (2, 256); m fast -> L2 sharing of weight rows
    fused_gemm_kernel<<<gg, 256>>>(weight, bias, sid, targets, san);
    loss_kernel<<<BSZ, 256>>>();
    final_kernel<<<1, 256>>>((float*)d_out);
}

// round 10
// speedup vs baseline: 1.9048x; 1.3086x over previous
#include <cuda_runtime.h>
#include <cuda_bf16.h>
#include <math.h>
#include <float.h>
#include <stdint.h>

#define BSZ 256
#define DIM 1024
#define SS  32768
#define NT  (SS / 128)

#define GBM 128
#define GBN 128
#define LDW 20              // 80 B smem row pitch (16 data words + 4 pad)
#define NSTG 4
#define STG_BYTES (GBM * LDW * 4)   // 10240 per stage per matrix
#define DSMEM (2 * NSTG * STG_BYTES)

// -------- device scratch (allocation-free rule) --------
__device__ __align__(16) __nv_bfloat16 g_xbf[(size_t)BSZ * DIM];   // 0.5 MB
__device__ __align__(16) __nv_bfloat16 g_wbf[(size_t)SS * DIM];    // 67 MB
__device__ float g_bg[SS];
__device__ float g_pz [(size_t)BSZ * NT];
__device__ float g_ptl[(size_t)BSZ * NT];
__device__ float g_pst[(size_t)BSZ * NT];
__device__ float g_row[BSZ];

// ---------------------------------------------------------------------------
__global__ void convert_x_kernel(const float* __restrict__ x)
{
    int i = blockIdx.x * blockDim.x + threadIdx.x;
    float4 v = ((const float4*)x)[i];
    __nv_bfloat162 p0 = __floats2bfloat162_rn(v.x, v.y);
    __nv_bfloat162 p1 = __floats2bfloat162_rn(v.z, v.w);
    uint2 o;
    o.x = *(const unsigned int*)&p0;
    o.y = *(const unsigned int*)&p1;
    ((uint2*)g_xbf)[i] = o;
}

// ---------------------------------------------------------------------------
// Gather sampled weight rows -> bf16 scratch; gather bias.
// ---------------------------------------------------------------------------
__global__ __launch_bounds__(256) void gather_kernel(const float* __restrict__ weight,
                                                     const float* __restrict__ bias,
                                                     const int* __restrict__ sid)
{
    int s = blockIdx.x;
    int t = threadIdx.x;
    int r = __ldg(&sid[s]);
    float4 v = ((const float4*)(weight + (size_t)r * DIM))[t];
    __nv_bfloat162 p0 = __floats2bfloat162_rn(v.x, v.y);
    __nv_bfloat162 p1 = __floats2bfloat162_rn(v.z, v.w);
    uint2 o;
    o.x = *(const unsigned int*)&p0;
    o.y = *(const unsigned int*)&p1;
    ((uint2*)(g_wbf + (size_t)s * DIM))[t] = o;
    if (t == 0) g_bg[s] = bias[r];
}

// ---------------------------------------------------------------------------
__device__ __forceinline__ void mma16816(float* d, const uint32_t* a, const uint32_t* b)
{
    asm volatile(
        "mma.sync.aligned.m16n8k16.row.col.f32.bf16.bf16.f32 "
        "{%0,%1,%2,%3},{%4,%5,%6,%7},{%8,%9},{%0,%1,%2,%3};"
        : "+f"(d[0]), "+f"(d[1]), "+f"(d[2]), "+f"(d[3])
        : "r"(a[0]), "r"(a[1]), "r"(a[2]), "r"(a[3]), "r"(b[0]), "r"(b[1]));
}
__device__ __forceinline__ uint32_t smem_u32(const void* p) {
    uint32_t a;
    asm("{ .reg .u64 t; cvta.to.shared.u64 t, %1; cvt.u32.u64 %0, t; }" : "=r"(a) : "l"(p));
    return a;
}
#define CP16(dst, src) \
    asm volatile("cp.async.cg.shared.global [%0], [%1], 16;" :: "r"(dst), "l"(src))
#define CP_COMMIT() asm volatile("cp.async.commit_group;" ::: "memory")
#define CP_WAIT(n)  asm volatile("cp.async.wait_group %0;" :: "n"(n) : "memory")

// ---------------------------------------------------------------------------
// Fused bf16 GEMM (4-stage cp.async) + bias + masked-softmax loss partials.
// grid (2, 256), 256 thr (8 warps, 2m x 4n), warp tile 64x32, BK=32.
// ---------------------------------------------------------------------------
__global__ __launch_bounds__(256, 2) void fused_gemm_kernel(
    const float* __restrict__ targets, const int* __restrict__ san)
{
    extern __shared__ char dyn[];
    uint32_t* sAp = (uint32_t*)dyn;                         // [4][128][20]
    uint32_t* sBp = (uint32_t*)(dyn + NSTG * STG_BYTES);
    __shared__ float sbias[GBN];

    const int tid  = threadIdx.x;
    const int m0   = blockIdx.x * GBM;
    const int n0   = blockIdx.y * GBN;
    const int bn   = blockIdx.y;
    const int wid  = tid >> 5;
    const int lane = tid & 31;
    const int wm   = (wid & 1) * 64;
    const int wn   = (wid >> 1) * 32;
    const int lr   = lane >> 2;
    const int lc   = lane & 3;

    if (tid < GBN) sbias[tid] = g_bg[n0 + tid];

    // load roles: 2 threads per row, 32 B (2 x 16 B) each per stage
    const int row_ld = tid >> 1;
    const int h_ld   = tid & 1;
    const char* gA = (const char*)(g_xbf + (size_t)(m0 + row_ld) * DIM);
    const char* gB = (const char*)(g_wbf + (size_t)(n0 + row_ld) * DIM);
    const uint32_t base = smem_u32(dyn);
    const uint32_t dstA = base + (row_ld * LDW + h_ld * 8) * 4;
    const uint32_t dstB = dstA + NSTG * STG_BYTES;

    float acc[4][4][4];
#pragma unroll
    for (int i = 0; i < 4; i++)
#pragma unroll
        for (int j = 0; j < 4; j++)
#pragma unroll
            for (int c = 0; c < 4; c++) acc[i][j][c] = 0.f;

    // prologue: stages 0..2
#pragma unroll
    for (int s = 0; s < NSTG - 1; s++) {
        CP16(dstA + s * STG_BYTES,      gA + s * 64 + h_ld * 32);
        CP16(dstA + s * STG_BYTES + 16, gA + s * 64 + h_ld * 32 + 16);
        CP16(dstB + s * STG_BYTES,      gB + s * 64 + h_ld * 32);
        CP16(dstB + s * STG_BYTES + 16, gB + s * 64 + h_ld * 32 + 16);
        CP_COMMIT();
    }

    const int NIT = DIM / 32;   // 32
    for (int it = 0; it < NIT; it++) {
        CP_WAIT(2);
        __syncthreads();

        const int ps = it + NSTG - 1;
        if (ps < NIT) {
            const int pb = ps & (NSTG - 1);
            CP16(dstA + pb * STG_BYTES,      gA + ps * 64 + h_ld * 32);
            CP16(dstA + pb * STG_BYTES + 16, gA + ps * 64 + h_ld * 32 + 16);
            CP16(dstB + pb * STG_BYTES,      gB + ps * 64 + h_ld * 32);
            CP16(dstB + pb * STG_BYTES + 16, gB + ps * 64 + h_ld * 32 + 16);
        }
        CP_COMMIT();

        const int buf = it & (NSTG - 1);
        const uint32_t* A = sAp + buf * (GBM * LDW);
        const uint32_t* B = sBp + buf * (GBN * LDW);

#pragma unroll
        for (int kk = 0; kk < 2; kk++) {
            const int ktw = kk * 8;
            uint32_t af[4][4], bfr[4][2];
#pragma unroll
            for (int mi = 0; mi < 4; mi++) {
                const int row = wm + mi * 16 + lr;
                af[mi][0] = A[row * LDW + ktw + lc];
                af[mi][1] = A[(row + 8) * LDW + ktw + lc];
                af[mi][2] = A[row * LDW + ktw + 4 + lc];
                af[mi][3] = A[(row + 8) * LDW + ktw + 4 + lc];
            }
#pragma unroll
            for (int nj = 0; nj < 4; nj++) {
                const int col = wn + nj * 8 + lr;
                bfr[nj][0] = B[col * LDW + ktw + lc];
                bfr[nj][1] = B[col * LDW + ktw + 4 + lc];
            }
#pragma unroll
            for (int mi = 0; mi < 4; mi++)
#pragma unroll
                for (int nj = 0; nj < 4; nj++)
                    mma16816(acc[mi][nj], af[mi], bfr[nj]);
        }
        __syncthreads();
    }

    // ---------------- fused loss epilogue ----------------
    CP_WAIT(0);
    __syncthreads();
    float* sz  = (float*)dyn;
    float* stl = sz + 512;
    float* sst = stl + 512;
    const int g = wid >> 1;

#pragma unroll
    for (int mi = 0; mi < 4; mi++) {
        const int row0 = m0 + wm + mi * 16 + lr;
        const int row1 = row0 + 8;
        const float* tp0 = targets + (size_t)row0 * SS + n0 + wn + 2 * lc;
        const float* tp1 = targets + (size_t)row1 * SS + n0 + wn + 2 * lc;
        const int*   sp0 = san + (size_t)row0 * SS + n0 + wn + 2 * lc;
        const int*   sp1 = san + (size_t)row1 * SS + n0 + wn + 2 * lc;

        float z0 = 0.f, z1 = 0.f, t0 = 0.f, t1 = 0.f, s0 = 0.f, s1 = 0.f;
#pragma unroll
        for (int nj = 0; nj < 4; nj++) {
            const float b0 = sbias[wn + nj * 8 + 2 * lc];
            const float b1 = sbias[wn + nj * 8 + 2 * lc + 1];
            float2 tv0 = *(const float2*)(tp0 + nj * 8);
            float2 tv1 = *(const float2*)(tp1 + nj * 8);
            int2   sv0 = *(const int2*)(sp0 + nj * 8);
            int2   sv1 = *(const int2*)(sp1 + nj * 8);

            float l00 = acc[mi][nj][0] + b0;
            float l01 = acc[mi][nj][1] + b1;
            float l10 = acc[mi][nj][2] + b0;
            float l11 = acc[mi][nj][3] + b1;

            if (sv0.x) z0 += __expf(l00);
            if (sv0.y) z0 += __expf(l01);
            if (sv1.x) z1 += __expf(l10);
            if (sv1.y) z1 += __expf(l11);

            t0 = fmaf(tv0.x, l00, t0); t0 = fmaf(tv0.y, l01, t0);
            t1 = fmaf(tv1.x, l10, t1); t1 = fmaf(tv1.y, l11, t1);
            s0 += tv0.x + tv0.y;
            s1 += tv1.x + tv1.y;
        }
#pragma unroll
        for (int o = 1; o <= 2; o <<= 1) {
            z0 += __shfl_xor_sync(0xffffffffu, z0, o);
            z1 += __shfl_xor_sync(0xffffffffu, z1, o);
            t0 += __shfl_xor_sync(0xffffffffu, t0, o);
            t1 += __shfl_xor_sync(0xffffffffu, t1, o);
            s0 += __shfl_xor_sync(0xffffffffu, s0, o);
            s1 += __shfl_xor_sync(0xffffffffu, s1, o);
        }
        if (lc == 0) {
            const int r0l = wm + mi * 16 + lr;
            sz [g * 128 + r0l]     = z0;
            sz [g * 128 + r0l + 8] = z1;
            stl[g * 128 + r0l]     = t0;
            stl[g * 128 + r0l + 8] = t1;
            sst[g * 128 + r0l]     = s0;
            sst[g * 128 + r0l + 8] = s1;
        }
    }
    __syncthreads();

    if (tid < GBM) {
        const size_t o = (size_t)(m0 + tid) * NT + bn;
        g_pz [o] = sz [tid] + sz [128 + tid] + sz [256 + tid] + sz [384 + tid];
        g_ptl[o] = stl[tid] + stl[128 + tid] + stl[256 + tid] + stl[384 + tid];
        g_pst[o] = sst[tid] + sst[128 + tid] + sst[256 + tid] + sst[384 + tid];
    }
}

// ---------------------------------------------------------------------------
__global__ __launch_bounds__(256) void loss_kernel()
{
    const int b = blockIdx.x;
    const int tid = threadIdx.x;
    float z  = g_pz [b * NT + tid];
    float tl = g_ptl[b * NT + tid];
    float st = g_pst[b * NT + tid];
#pragma unroll
    for (int o = 16; o; o >>= 1) {
        z  += __shfl_xor_sync(0xffffffffu, z, o);
        tl += __shfl_xor_sync(0xffffffffu, tl, o);
        st += __shfl_xor_sync(0xffffffffu, st, o);
    }
    __shared__ float rz[8], rtl[8], rst[8];
    if ((tid & 31) == 0) { rz[tid >> 5] = z; rtl[tid >> 5] = tl; rst[tid >> 5] = st; }
    __syncthreads();
    if (tid < 32) {
        z  = (tid < 8) ? rz[tid]  : 0.f;
        tl = (tid < 8) ? rtl[tid] : 0.f;
        st = (tid < 8) ? rst[tid] : 0.f;
#pragma unroll
        for (int o = 4; o; o >>= 1) {
            z  += __shfl_xor_sync(0xffffffffu, z, o);
            tl += __shfl_xor_sync(0xffffffffu, tl, o);
            st += __shfl_xor_sync(0xffffffffu, st, o);
        }
        if (tid == 0) g_row[b] = logf(z) * st - tl;
    }
}

__global__ void final_kernel(float* __restrict__ out)
{
    __shared__ float red[256];
    int tid = threadIdx.x;
    red[tid] = g_row[tid];
    __syncthreads();
    for (int off = 128; off; off >>= 1) {
        if (tid < off) red[tid] += red[tid + off];
        __syncthreads();
    }
    if (tid == 0) out[0] = red[0] / (float)BSZ;
}

extern "C" void kernel_launch(void* const* d_in, const int* in_sizes, int n_in,
                              void* d_out, int out_size)
{
    const float* x       = (const float*)d_in[0];
    const float* weight  = (const float*)d_in[1];
    const float* bias    = (const float*)d_in[2];
    const float* targets = (const float*)d_in[3];
    const int*   sid     = (const int*)d_in[4];
    const int*   san     = (const int*)d_in[5];

    cudaFuncSetAttribute(fused_gemm_kernel,
                         cudaFuncAttributeMaxDynamicSharedMemorySize, DSMEM);
    convert_x_kernel<<<(BSZ * DIM / 4) / 256, 256>>>(x);
    gather_kernel<<<SS, 256>>>(weight, bias, sid);
    dim3 gg(BSZ / GBM, SS / GBN);   // (2, 256); m fast -> L2 sharing of w rows
    fused_gemm_kernel<<<gg, 256, DSMEM>>>(targets, san);
    loss_kernel<<<BSZ, 256>>>();
    final_kernel<<<1, 256>>>((float*)d_out);
}

// round 11
// speedup vs baseline: 1.9099x; 1.0026x over previous
#include <cuda_runtime.h>
#include <cuda_bf16.h>
#include <math.h>
#include <float.h>
#include <stdint.h>

#define BSZ 256
#define DIM 1024
#define SS  32768
#define NT  (SS / 128)

#define GBM 128
#define GBN 128
#define LDW  20    // bf16 smem pitch: 16 data words + 4 pad (80 B)
#define PF32 36    // fp32 staging pitch: 32 data words + 4 pad (144 B)

#define ASTG_W   (GBM * LDW)
#define BF32STG_W (GBN * PF32)
#define BB16STG_W (GBN * LDW)
#define A_OFF    0
#define BF32_OFF (3 * ASTG_W * 4)
#define BB16_OFF (BF32_OFF + 3 * BF32STG_W * 4)
#define DSMEM    (BB16_OFF + 2 * BB16STG_W * 4)   // 106,496 B

// -------- device scratch (allocation-free rule) --------
__device__ __align__(16) __nv_bfloat16 g_xbf[(size_t)BSZ * DIM];   // 0.5 MB, L2-resident
__device__ float g_pz [(size_t)BSZ * NT];
__device__ float g_ptl[(size_t)BSZ * NT];
__device__ float g_pst[(size_t)BSZ * NT];
__device__ float g_row[BSZ];
__device__ int   g_cnt;

// ---------------------------------------------------------------------------
__global__ void convert_x_kernel(const float* __restrict__ x)
{
    if (blockIdx.x == 0 && threadIdx.x == 0) g_cnt = 0;
    int i = blockIdx.x * blockDim.x + threadIdx.x;
    float4 v = ((const float4*)x)[i];
    __nv_bfloat162 p0 = __floats2bfloat162_rn(v.x, v.y);
    __nv_bfloat162 p1 = __floats2bfloat162_rn(v.z, v.w);
    uint2 o;
    o.x = *(const unsigned int*)&p0;
    o.y = *(const unsigned int*)&p1;
    ((uint2*)g_xbf)[i] = o;
}

__device__ __forceinline__ void mma16816(float* d, const uint32_t* a, const uint32_t* b)
{
    asm volatile(
        "mma.sync.aligned.m16n8k16.row.col.f32.bf16.bf16.f32 "
        "{%0,%1,%2,%3},{%4,%5,%6,%7},{%8,%9},{%0,%1,%2,%3};"
        : "+f"(d[0]), "+f"(d[1]), "+f"(d[2]), "+f"(d[3])
        : "r"(a[0]), "r"(a[1]), "r"(a[2]), "r"(a[3]), "r"(b[0]), "r"(b[1]));
}
__device__ __forceinline__ uint32_t smem_u32(const void* p) {
    uint32_t a;
    asm("{ .reg .u64 t; cvta.to.shared.u64 t, %1; cvt.u32.u64 %0, t; }" : "=r"(a) : "l"(p));
    return a;
}
#define CP16(dst, src) \
    asm volatile("cp.async.cg.shared.global [%0], [%1], 16;" :: "r"(dst), "l"(src))
#define CP_COMMIT() asm volatile("cp.async.commit_group;" ::: "memory")
#define CP_WAIT(n)  asm volatile("cp.async.wait_group %0;" :: "n"(n) : "memory")

// ---------------------------------------------------------------------------
// Fully fused: gathered fp32 weight rows -> smem (cp.async, 3-stage) ->
// in-loop bf16 conversion -> bf16 HMMA GEMM -> bias + masked-softmax loss
// partials. grid (2, 256), 256 thr (8 warps, 2m x 4n), warp tile 64x32, BK=32.
// ---------------------------------------------------------------------------
__global__ __launch_bounds__(256, 2) void fused_gemm_kernel(
    const float* __restrict__ weight, const float* __restrict__ bias,
    const int* __restrict__ sid,
    const float* __restrict__ targets, const int* __restrict__ san)
{
    extern __shared__ char dyn[];
    uint32_t* sAp   = (uint32_t*)(dyn + A_OFF);     // [3][128][20] bf16 pairs
    float*    sBf32 = (float*)(dyn + BF32_OFF);     // [3][128][36] fp32
    uint32_t* sBb16 = (uint32_t*)(dyn + BB16_OFF);  // [2][128][20] bf16 pairs
    __shared__ float sbias[GBN];
    __shared__ int   srid[GBN];

    const int tid  = threadIdx.x;
    const int m0   = blockIdx.x * GBM;
    const int n0   = blockIdx.y * GBN;
    const int bn   = blockIdx.y;
    const int wid  = tid >> 5;
    const int lane = tid & 31;
    const int wm   = (wid & 1) * 64;
    const int wn   = (wid >> 1) * 32;
    const int lr   = lane >> 2;
    const int lc   = lane & 3;

    if (tid < GBN) {
        int r = __ldg(&sid[n0 + tid]);
        srid[tid] = r;
        sbias[tid] = bias[r];
    }
    __syncthreads();

    // cp.async roles: 2 threads per row
    const int row_ld = tid >> 1;
    const int h_ld   = tid & 1;
    const char* gA = (const char*)(g_xbf + (size_t)(m0 + row_ld) * DIM);
    const char* gB = (const char*)(weight + (size_t)srid[row_ld] * DIM);
    const uint32_t base = smem_u32(dyn);
    const uint32_t dA = base + A_OFF    + (row_ld * LDW  + h_ld * 8)  * 4;
    const uint32_t dB = base + BF32_OFF + (row_ld * PF32 + h_ld * 16) * 4;

    // conversion roles: 1 thread per row-half
    const int crow = tid & 127;
    const int ch   = tid >> 7;

    float acc[4][4][4];
#pragma unroll
    for (int i = 0; i < 4; i++)
#pragma unroll
        for (int j = 0; j < 4; j++)
#pragma unroll
            for (int c = 0; c < 4; c++) acc[i][j][c] = 0.f;

    // prologue: stages 0, 1
#pragma unroll
    for (int s = 0; s < 2; s++) {
        CP16(dA + s * (ASTG_W * 4),      gA + s * 64 + h_ld * 32);
        CP16(dA + s * (ASTG_W * 4) + 16, gA + s * 64 + h_ld * 32 + 16);
#pragma unroll
        for (int j = 0; j < 4; j++)
            CP16(dB + s * (BF32STG_W * 4) + j * 16, gB + s * 128 + h_ld * 64 + j * 16);
        CP_COMMIT();
    }

    const int NIT = DIM / 32;   // 32
    for (int it = 0; it < NIT; it++) {
        CP_WAIT(1);             // stage it arrived
        __syncthreads();

        const int ps = it + 2;
        if (ps < NIT) {
            const int pb = ps % 3;
            CP16(dA + pb * (ASTG_W * 4),      gA + ps * 64 + h_ld * 32);
            CP16(dA + pb * (ASTG_W * 4) + 16, gA + ps * 64 + h_ld * 32 + 16);
#pragma unroll
            for (int j = 0; j < 4; j++)
                CP16(dB + pb * (BF32STG_W * 4) + j * 16, gB + ps * 128 + h_ld * 64 + j * 16);
        }
        CP_COMMIT();

        // convert B fp32 stage it -> bf16 phase it&1
        {
            const float* f = sBf32 + (it % 3) * BF32STG_W + crow * PF32 + ch * 16;
            float4 c0 = *(const float4*)(f + 0);
            float4 c1 = *(const float4*)(f + 4);
            float4 c2 = *(const float4*)(f + 8);
            float4 c3 = *(const float4*)(f + 12);
            uint4 o0, o1;
            __nv_bfloat162 t;
            t = __floats2bfloat162_rn(c0.x, c0.y); o0.x = *(unsigned*)&t;
            t = __floats2bfloat162_rn(c0.z, c0.w); o0.y = *(unsigned*)&t;
            t = __floats2bfloat162_rn(c1.x, c1.y); o0.z = *(unsigned*)&t;
            t = __floats2bfloat162_rn(c1.z, c1.w); o0.w = *(unsigned*)&t;
            t = __floats2bfloat162_rn(c2.x, c2.y); o1.x = *(unsigned*)&t;
            t = __floats2bfloat162_rn(c2.z, c2.w); o1.y = *(unsigned*)&t;
            t = __floats2bfloat162_rn(c3.x, c3.y); o1.z = *(unsigned*)&t;
            t = __floats2bfloat162_rn(c3.z, c3.w); o1.w = *(unsigned*)&t;
            uint32_t* d = sBb16 + (it & 1) * BB16STG_W + crow * LDW + ch * 8;
            *(uint4*)(d + 0) = o0;
            *(uint4*)(d + 4) = o1;
        }
        __syncthreads();

        const uint32_t* A = sAp + (it % 3) * ASTG_W;
        const uint32_t* B = sBb16 + (it & 1) * BB16STG_W;

#pragma unroll
        for (int kk = 0; kk < 2; kk++) {
            const int ktw = kk * 8;
            uint32_t af[4][4], bfr[4][2];
#pragma unroll
            for (int mi = 0; mi < 4; mi++) {
                const int row = wm + mi * 16 + lr;
                af[mi][0] = A[row * LDW + ktw + lc];
                af[mi][1] = A[(row + 8) * LDW + ktw + lc];
                af[mi][2] = A[row * LDW + ktw + 4 + lc];
                af[mi][3] = A[(row + 8) * LDW + ktw + 4 + lc];
            }
#pragma unroll
            for (int nj = 0; nj < 4; nj++) {
                const int col = wn + nj * 8 + lr;
                bfr[nj][0] = B[col * LDW + ktw + lc];
                bfr[nj][1] = B[col * LDW + ktw + 4 + lc];
            }
#pragma unroll
            for (int mi = 0; mi < 4; mi++)
#pragma unroll
                for (int nj = 0; nj < 4; nj++)
                    mma16816(acc[mi][nj], af[mi], bfr[nj]);
        }
    }

    // ---------------- fused loss epilogue ----------------
    CP_WAIT(0);
    __syncthreads();
    float* sz  = (float*)dyn;
    float* stl = sz + 512;
    float* sst = stl + 512;
    const int g = wid >> 1;

#pragma unroll
    for (int mi = 0; mi < 4; mi++) {
        const int row0 = m0 + wm + mi * 16 + lr;
        const int row1 = row0 + 8;
        const float* tp0 = targets + (size_t)row0 * SS + n0 + wn + 2 * lc;
        const float* tp1 = targets + (size_t)row1 * SS + n0 + wn + 2 * lc;
        const int*   sp0 = san + (size_t)row0 * SS + n0 + wn + 2 * lc;
        const int*   sp1 = san + (size_t)row1 * SS + n0 + wn + 2 * lc;

        float z0 = 0.f, z1 = 0.f, t0 = 0.f, t1 = 0.f, s0 = 0.f, s1 = 0.f;
#pragma unroll
        for (int nj = 0; nj < 4; nj++) {
            const float b0 = sbias[wn + nj * 8 + 2 * lc];
            const float b1 = sbias[wn + nj * 8 + 2 * lc + 1];
            float2 tv0 = *(const float2*)(tp0 + nj * 8);
            float2 tv1 = *(const float2*)(tp1 + nj * 8);
            int2   sv0 = *(const int2*)(sp0 + nj * 8);
            int2   sv1 = *(const int2*)(sp1 + nj * 8);

            float l00 = acc[mi][nj][0] + b0;
            float l01 = acc[mi][nj][1] + b1;
            float l10 = acc[mi][nj][2] + b0;
            float l11 = acc[mi][nj][3] + b1;

            if (sv0.x) z0 += __expf(l00);
            if (sv0.y) z0 += __expf(l01);
            if (sv1.x) z1 += __expf(l10);
            if (sv1.y) z1 += __expf(l11);

            t0 = fmaf(tv0.x, l00, t0); t0 = fmaf(tv0.y, l01, t0);
            t1 = fmaf(tv1.x, l10, t1); t1 = fmaf(tv1.y, l11, t1);
            s0 += tv0.x + tv0.y;
            s1 += tv1.x + tv1.y;
        }
#pragma unroll
        for (int o = 1; o <= 2; o <<= 1) {
            z0 += __shfl_xor_sync(0xffffffffu, z0, o);
            z1 += __shfl_xor_sync(0xffffffffu, z1, o);
            t0 += __shfl_xor_sync(0xffffffffu, t0, o);
            t1 += __shfl_xor_sync(0xffffffffu, t1, o);
            s0 += __shfl_xor_sync(0xffffffffu, s0, o);
            s1 += __shfl_xor_sync(0xffffffffu, s1, o);
        }
        if (lc == 0) {
            const int r0l = wm + mi * 16 + lr;
            sz [g * 128 + r0l]     = z0;
            sz [g * 128 + r0l + 8] = z1;
            stl[g * 128 + r0l]     = t0;
            stl[g * 128 + r0l + 8] = t1;
            sst[g * 128 + r0l]     = s0;
            sst[g * 128 + r0l + 8] = s1;
        }
    }
    __syncthreads();

    if (tid < GBM) {
        const size_t o = (size_t)(m0 + tid) * NT + bn;
        g_pz [o] = sz [tid] + sz [128 + tid] + sz [256 + tid] + sz [384 + tid];
        g_ptl[o] = stl[tid] + stl[128 + tid] + stl[256 + tid] + stl[384 + tid];
        g_pst[o] = sst[tid] + sst[128 + tid] + sst[256 + tid] + sst[384 + tid];
    }
}

// ---------------------------------------------------------------------------
// Loss per row (256 blocks) + last block computes the mean (atomic counter).
// ---------------------------------------------------------------------------
__global__ __launch_bounds__(256) void loss_kernel(float* __restrict__ out)
{
    const int b = blockIdx.x;
    const int tid = threadIdx.x;
    float z  = g_pz [b * NT + tid];
    float tl = g_ptl[b * NT + tid];
    float st = g_pst[b * NT + tid];
#pragma unroll
    for (int o = 16; o; o >>= 1) {
        z  += __shfl_xor_sync(0xffffffffu, z, o);
        tl += __shfl_xor_sync(0xffffffffu, tl, o);
        st += __shfl_xor_sync(0xffffffffu, st, o);
    }
    __shared__ float rz[8], rtl[8], rst[8];
    __shared__ int slast;
    if ((tid & 31) == 0) { rz[tid >> 5] = z; rtl[tid >> 5] = tl; rst[tid >> 5] = st; }
    __syncthreads();
    if (tid < 32) {
        z  = (tid < 8) ? rz[tid]  : 0.f;
        tl = (tid < 8) ? rtl[tid] : 0.f;
        st = (tid < 8) ? rst[tid] : 0.f;
#pragma unroll
        for (int o = 4; o; o >>= 1) {
            z  += __shfl_xor_sync(0xffffffffu, z, o);
            tl += __shfl_xor_sync(0xffffffffu, tl, o);
            st += __shfl_xor_sync(0xffffffffu, st, o);
        }
        if (tid == 0) {
            g_row[b] = logf(z) * st - tl;
            __threadfence();
            slast = (atomicAdd(&g_cnt, 1) == BSZ - 1);
        }
    }
    __syncthreads();
    if (slast) {   // deterministic: mean over fixed values in fixed order
        __shared__ float red[256];
        __threadfence();
        red[tid] = *((volatile float*)&g_row[tid]);
        __syncthreads();
        for (int off = 128; off; off >>= 1) {
            if (tid < off) red[tid] += red[tid + off];
            __syncthreads();
        }
        if (tid == 0) out[0] = red[0] / (float)BSZ;
    }
}

extern "C" void kernel_launch(void* const* d_in, const int* in_sizes, int n_in,
                              void* d_out, int out_size)
{
    const float* x       = (const float*)d_in[0];
    const float* weight  = (const float*)d_in[1];
    const float* bias    = (const float*)d_in[2];
    const float* targets = (const float*)d_in[3];
    const int*   sid     = (const int*)d_in[4];
    const int*   san     = (const int*)d_in[5];

    cudaFuncSetAttribute(fused_gemm_kernel,
                         cudaFuncAttributeMaxDynamicSharedMemorySize, DSMEM);
    convert_x_kernel<<<(BSZ * DIM / 4) / 256, 256>>>(x);
    dim3 gg(BSZ / GBM, SS / GBN);   // (2, 256); m fast -> L2 sharing of weight rows
    fused_gemm_kernel<<<gg, 256, DSMEM>>>(weight, bias, sid, targets, san);
    loss_kernel<<<BSZ, 256>>>((float*)d_out);
}

// round 12
// speedup vs baseline: 2.0491x; 1.0729x over previous
#include <cuda_runtime.h>
#include <cuda_bf16.h>
#include <math.h>
#include <float.h>
#include <stdint.h>

#define BSZ 256
#define DIM 1024
#define SS  32768
#define NT  (SS / 128)

#define GBM 128
#define GBN 128
#define LDW  20    // bf16 smem pitch: 16 data words + 4 pad (80 B)
#define PF32 36    // fp32 staging pitch: 32 data words + 4 pad (144 B)

#define ASTG_W    (GBM * LDW)
#define BF32STG_W (GBN * PF32)
#define BB16STG_W (GBN * LDW)
#define A_OFF    0
#define BF32_OFF (3 * ASTG_W * 4)
#define BB16_OFF (BF32_OFF + 3 * BF32STG_W * 4)
#define DSMEM    (BB16_OFF + 2 * BB16STG_W * 4)   // 106,496 B

// -------- device scratch (allocation-free rule) --------
__device__ __align__(16) __nv_bfloat16 g_xbf[(size_t)BSZ * DIM];   // 0.5 MB, L2-resident
__device__ float g_pz [(size_t)BSZ * NT];
__device__ float g_ptl[(size_t)BSZ * NT];
__device__ float g_pst[(size_t)BSZ * NT];
__device__ float g_row[BSZ];
__device__ int   g_cnt;

// ---------------------------------------------------------------------------
__global__ void convert_x_kernel(const float* __restrict__ x)
{
    if (blockIdx.x == 0 && threadIdx.x == 0) g_cnt = 0;
    int i = blockIdx.x * blockDim.x + threadIdx.x;
    float4 v = ((const float4*)x)[i];
    __nv_bfloat162 p0 = __floats2bfloat162_rn(v.x, v.y);
    __nv_bfloat162 p1 = __floats2bfloat162_rn(v.z, v.w);
    uint2 o;
    o.x = *(const unsigned int*)&p0;
    o.y = *(const unsigned int*)&p1;
    ((uint2*)g_xbf)[i] = o;
}

__device__ __forceinline__ void mma16816(float* d, const uint32_t* a, const uint32_t* b)
{
    asm volatile(
        "mma.sync.aligned.m16n8k16.row.col.f32.bf16.bf16.f32 "
        "{%0,%1,%2,%3},{%4,%5,%6,%7},{%8,%9},{%0,%1,%2,%3};"
        : "+f"(d[0]), "+f"(d[1]), "+f"(d[2]), "+f"(d[3])
        : "r"(a[0]), "r"(a[1]), "r"(a[2]), "r"(a[3]), "r"(b[0]), "r"(b[1]));
}
__device__ __forceinline__ uint32_t smem_u32(const void* p) {
    uint32_t a;
    asm("{ .reg .u64 t; cvta.to.shared.u64 t, %1; cvt.u32.u64 %0, t; }" : "=r"(a) : "l"(p));
    return a;
}
#define CP16(dst, src) \
    asm volatile("cp.async.cg.shared.global [%0], [%1], 16;" :: "r"(dst), "l"(src))
#define CP_COMMIT() asm volatile("cp.async.commit_group;" ::: "memory")
#define CP_WAIT(n)  asm volatile("cp.async.wait_group %0;" :: "n"(n) : "memory")

// ---------------------------------------------------------------------------
// Fully fused: gathered fp32 weight rows -> smem (cp.async, 3-stage) ->
// pipelined bf16 conversion (1 stage ahead, in HMMA shadow) -> bf16 GEMM ->
// bias + masked-softmax loss partials.
// grid (2, 256), 256 thr (8 warps, 2m x 4n), warp tile 64x32, BK=32.
// One __syncthreads per mainloop iteration.
// ---------------------------------------------------------------------------
__global__ __launch_bounds__(256, 2) void fused_gemm_kernel(
    const float* __restrict__ weight, const float* __restrict__ bias,
    const int* __restrict__ sid,
    const float* __restrict__ targets, const int* __restrict__ san)
{
    extern __shared__ char dyn[];
    uint32_t* sAp   = (uint32_t*)(dyn + A_OFF);     // [3][128][20] bf16 pairs
    float*    sBf32 = (float*)(dyn + BF32_OFF);     // [3][128][36] fp32
    uint32_t* sBb16 = (uint32_t*)(dyn + BB16_OFF);  // [2][128][20] bf16 pairs
    __shared__ float sbias[GBN];
    __shared__ int   srid[GBN];

    const int tid  = threadIdx.x;
    const int m0   = blockIdx.x * GBM;
    const int n0   = blockIdx.y * GBN;
    const int bn   = blockIdx.y;
    const int wid  = tid >> 5;
    const int lane = tid & 31;
    const int wm   = (wid & 1) * 64;
    const int wn   = (wid >> 1) * 32;
    const int lr   = lane >> 2;
    const int lc   = lane & 3;

    if (tid < GBN) {
        int r = __ldg(&sid[n0 + tid]);
        srid[tid] = r;
        sbias[tid] = bias[r];
    }
    __syncthreads();

    // cp.async roles: 2 threads per row
    const int row_ld = tid >> 1;
    const int h_ld   = tid & 1;
    const char* gA = (const char*)(g_xbf + (size_t)(m0 + row_ld) * DIM);
    const char* gB = (const char*)(weight + (size_t)srid[row_ld] * DIM);
    const uint32_t base = smem_u32(dyn);
    const uint32_t dA = base + A_OFF    + (row_ld * LDW  + h_ld * 8)  * 4;
    const uint32_t dB = base + BF32_OFF + (row_ld * PF32 + h_ld * 16) * 4;

    // conversion roles: 1 thread per row-half
    const int crow = tid & 127;
    const int ch   = tid >> 7;

    float acc[4][4][4];
#pragma unroll
    for (int i = 0; i < 4; i++)
#pragma unroll
        for (int j = 0; j < 4; j++)
#pragma unroll
            for (int c = 0; c < 4; c++) acc[i][j][c] = 0.f;

    // prologue: stages 0, 1 in flight
#pragma unroll
    for (int s = 0; s < 2; s++) {
        CP16(dA + s * (ASTG_W * 4),      gA + s * 64 + h_ld * 32);
        CP16(dA + s * (ASTG_W * 4) + 16, gA + s * 64 + h_ld * 32 + 16);
#pragma unroll
        for (int j = 0; j < 4; j++)
            CP16(dB + s * (BF32STG_W * 4) + j * 16, gB + s * 128 + h_ld * 64 + j * 16);
        CP_COMMIT();
    }
    // stage 0 ready -> convert to bbuf 0
    CP_WAIT(1);
    __syncthreads();
    {
        const float* f = sBf32 + 0 * BF32STG_W + crow * PF32 + ch * 16;
        float4 c0 = *(const float4*)(f + 0);
        float4 c1 = *(const float4*)(f + 4);
        float4 c2 = *(const float4*)(f + 8);
        float4 c3 = *(const float4*)(f + 12);
        uint4 o0, o1;
        __nv_bfloat162 t;
        t = __floats2bfloat162_rn(c0.x, c0.y); o0.x = *(unsigned*)&t;
        t = __floats2bfloat162_rn(c0.z, c0.w); o0.y = *(unsigned*)&t;
        t = __floats2bfloat162_rn(c1.x, c1.y); o0.z = *(unsigned*)&t;
        t = __floats2bfloat162_rn(c1.z, c1.w); o0.w = *(unsigned*)&t;
        t = __floats2bfloat162_rn(c2.x, c2.y); o1.x = *(unsigned*)&t;
        t = __floats2bfloat162_rn(c2.z, c2.w); o1.y = *(unsigned*)&t;
        t = __floats2bfloat162_rn(c3.x, c3.y); o1.z = *(unsigned*)&t;
        t = __floats2bfloat162_rn(c3.z, c3.w); o1.w = *(unsigned*)&t;
        uint32_t* d = sBb16 + 0 * BB16STG_W + crow * LDW + ch * 8;
        *(uint4*)(d + 0) = o0;
        *(uint4*)(d + 4) = o1;
    }

    const int NIT = DIM / 32;   // 32
    for (int it = 0; it < NIT; it++) {
        // prefetch stage it+2 (slot held stage it-1, consumed 2 barriers ago)
        const int ps = it + 2;
        if (ps < NIT) {
            const int pb = ps % 3;
            CP16(dA + pb * (ASTG_W * 4),      gA + ps * 64 + h_ld * 32);
            CP16(dA + pb * (ASTG_W * 4) + 16, gA + ps * 64 + h_ld * 32 + 16);
#pragma unroll
            for (int j = 0; j < 4; j++)
                CP16(dB + pb * (BF32STG_W * 4) + j * 16, gB + ps * 128 + h_ld * 64 + j * 16);
        }
        CP_COMMIT();
        CP_WAIT(1);             // stage it+1 (A and B fp32) arrived
        __syncthreads();        // visibility: stage it+1 + bbuf[it&1] conversion

        // ---- MMA on buffer converted last iteration (issued first) ----
        const uint32_t* A = sAp + (it % 3) * ASTG_W;
        const uint32_t* B = sBb16 + (it & 1) * BB16STG_W;
#pragma unroll
        for (int kk = 0; kk < 2; kk++) {
            const int ktw = kk * 8;
            uint32_t af[4][4], bfr[4][2];
#pragma unroll
            for (int mi = 0; mi < 4; mi++) {
                const int row = wm + mi * 16 + lr;
                af[mi][0] = A[row * LDW + ktw + lc];
                af[mi][1] = A[(row + 8) * LDW + ktw + lc];
                af[mi][2] = A[row * LDW + ktw + 4 + lc];
                af[mi][3] = A[(row + 8) * LDW + ktw + 4 + lc];
            }
#pragma unroll
            for (int nj = 0; nj < 4; nj++) {
                const int col = wn + nj * 8 + lr;
                bfr[nj][0] = B[col * LDW + ktw + lc];
                bfr[nj][1] = B[col * LDW + ktw + 4 + lc];
            }
#pragma unroll
            for (int mi = 0; mi < 4; mi++)
#pragma unroll
                for (int nj = 0; nj < 4; nj++)
                    mma16816(acc[mi][nj], af[mi], bfr[nj]);
        }

        // ---- convert stage it+1 -> bbuf[(it+1)&1], in the HMMA shadow ----
        if (it + 1 < NIT) {
            const float* f = sBf32 + ((it + 1) % 3) * BF32STG_W + crow * PF32 + ch * 16;
            float4 c0 = *(const float4*)(f + 0);
            float4 c1 = *(const float4*)(f + 4);
            float4 c2 = *(const float4*)(f + 8);
            float4 c3 = *(const float4*)(f + 12);
            uint4 o0, o1;
            __nv_bfloat162 t;
            t = __floats2bfloat162_rn(c0.x, c0.y); o0.x = *(unsigned*)&t;
            t = __floats2bfloat162_rn(c0.z, c0.w); o0.y = *(unsigned*)&t;
            t = __floats2bfloat162_rn(c1.x, c1.y); o0.z = *(unsigned*)&t;
            t = __floats2bfloat162_rn(c1.z, c1.w); o0.w = *(unsigned*)&t;
            t = __floats2bfloat162_rn(c2.x, c2.y); o1.x = *(unsigned*)&t;
            t = __floats2bfloat162_rn(c2.z, c2.w); o1.y = *(unsigned*)&t;
            t = __floats2bfloat162_rn(c3.x, c3.y); o1.z = *(unsigned*)&t;
            t = __floats2bfloat162_rn(c3.z, c3.w); o1.w = *(unsigned*)&t;
            uint32_t* d = sBb16 + ((it + 1) & 1) * BB16STG_W + crow * LDW + ch * 8;
            *(uint4*)(d + 0) = o0;
            *(uint4*)(d + 4) = o1;
        }
    }

    // ---------------- fused loss epilogue ----------------
    CP_WAIT(0);
    __syncthreads();
    float* sz  = (float*)dyn;
    float* stl = sz + 512;
    float* sst = stl + 512;
    const int g = wid >> 1;

#pragma unroll
    for (int mi = 0; mi < 4; mi++) {
        const int row0 = m0 + wm + mi * 16 + lr;
        const int row1 = row0 + 8;
        const float* tp0 = targets + (size_t)row0 * SS + n0 + wn + 2 * lc;
        const float* tp1 = targets + (size_t)row1 * SS + n0 + wn + 2 * lc;
        const int*   sp0 = san + (size_t)row0 * SS + n0 + wn + 2 * lc;
        const int*   sp1 = san + (size_t)row1 * SS + n0 + wn + 2 * lc;

        float z0 = 0.f, z1 = 0.f, t0 = 0.f, t1 = 0.f, s0 = 0.f, s1 = 0.f;
#pragma unroll
        for (int nj = 0; nj < 4; nj++) {
            const float b0 = sbias[wn + nj * 8 + 2 * lc];
            const float b1 = sbias[wn + nj * 8 + 2 * lc + 1];
            float2 tv0 = *(const float2*)(tp0 + nj * 8);
            float2 tv1 = *(const float2*)(tp1 + nj * 8);
            int2   sv0 = *(const int2*)(sp0 + nj * 8);
            int2   sv1 = *(const int2*)(sp1 + nj * 8);

            float l00 = acc[mi][nj][0] + b0;
            float l01 = acc[mi][nj][1] + b1;
            float l10 = acc[mi][nj][2] + b0;
            float l11 = acc[mi][nj][3] + b1;

            if (sv0.x) z0 += __expf(l00);
            if (sv0.y) z0 += __expf(l01);
            if (sv1.x) z1 += __expf(l10);
            if (sv1.y) z1 += __expf(l11);

            t0 = fmaf(tv0.x, l00, t0); t0 = fmaf(tv0.y, l01, t0);
            t1 = fmaf(tv1.x, l10, t1); t1 = fmaf(tv1.y, l11, t1);
            s0 += tv0.x + tv0.y;
            s1 += tv1.x + tv1.y;
        }
#pragma unroll
        for (int o = 1; o <= 2; o <<= 1) {
            z0 += __shfl_xor_sync(0xffffffffu, z0, o);
            z1 += __shfl_xor_sync(0xffffffffu, z1, o);
            t0 += __shfl_xor_sync(0xffffffffu, t0, o);
            t1 += __shfl_xor_sync(0xffffffffu, t1, o);
            s0 += __shfl_xor_sync(0xffffffffu, s0, o);
            s1 += __shfl_xor_sync(0xffffffffu, s1, o);
        }
        if (lc == 0) {
            const int r0l = wm + mi * 16 + lr;
            sz [g * 128 + r0l]     = z0;
            sz [g * 128 + r0l + 8] = z1;
            stl[g * 128 + r0l]     = t0;
            stl[g * 128 + r0l + 8] = t1;
            sst[g * 128 + r0l]     = s0;
            sst[g * 128 + r0l + 8] = s1;
        }
    }
    __syncthreads();

    if (tid < GBM) {
        const size_t o = (size_t)(m0 + tid) * NT + bn;
        g_pz [o] = sz [tid] + sz [128 + tid] + sz [256 + tid] + sz [384 + tid];
        g_ptl[o] = stl[tid] + stl[128 + tid] + stl[256 + tid] + stl[384 + tid];
        g_pst[o] = sst[tid] + sst[128 + tid] + sst[256 + tid] + sst[384 + tid];
    }
}

// ---------------------------------------------------------------------------
// Loss per row (256 blocks) + last block computes the mean (atomic counter).
// ---------------------------------------------------------------------------
__global__ __launch_bounds__(256) void loss_kernel(float* __restrict__ out)
{
    const int b = blockIdx.x;
    const int tid = threadIdx.x;
    float z  = g_pz [b * NT + tid];
    float tl = g_ptl[b * NT + tid];
    float st = g_pst[b * NT + tid];
#pragma unroll
    for (int o = 16; o; o >>= 1) {
        z  += __shfl_xor_sync(0xffffffffu, z, o);
        tl += __shfl_xor_sync(0xffffffffu, tl, o);
        st += __shfl_xor_sync(0xffffffffu, st, o);
    }
    __shared__ float rz[8], rtl[8], rst[8];
    __shared__ int slast;
    if ((tid & 31) == 0) { rz[tid >> 5] = z; rtl[tid >> 5] = tl; rst[tid >> 5] = st; }
    __syncthreads();
    if (tid < 32) {
        z  = (tid < 8) ? rz[tid]  : 0.f;
        tl = (tid < 8) ? rtl[tid] : 0.f;
        st = (tid < 8) ? rst[tid] : 0.f;
#pragma unroll
        for (int o = 4; o; o >>= 1) {
            z  += __shfl_xor_sync(0xffffffffu, z, o);
            tl += __shfl_xor_sync(0xffffffffu, tl, o);
            st += __shfl_xor_sync(0xffffffffu, st, o);
        }
        if (tid == 0) {
            g_row[b] = logf(z) * st - tl;
            __threadfence();
            slast = (atomicAdd(&g_cnt, 1) == BSZ - 1);
        }
    }
    __syncthreads();
    if (slast) {   // deterministic: mean over fixed values in fixed order
        __shared__ float red[256];
        __threadfence();
        red[tid] = *((volatile float*)&g_row[tid]);
        __syncthreads();
        for (int off = 128; off; off >>= 1) {
            if (tid < off) red[tid] += red[tid + off];
            __syncthreads();
        }
        if (tid == 0) out[0] = red[0] / (float)BSZ;
    }
}

extern "C" void kernel_launch(void* const* d_in, const int* in_sizes, int n_in,
                              void* d_out, int out_size)
{
    const float* x       = (const float*)d_in[0];
    const float* weight  = (const float*)d_in[1];
    const float* bias    = (const float*)d_in[2];
    const float* targets = (const float*)d_in[3];
    const int*   sid     = (const int*)d_in[4];
    const int*   san     = (const int*)d_in[5];

    cudaFuncSetAttribute(fused_gemm_kernel,
                         cudaFuncAttributeMaxDynamicSharedMemorySize, DSMEM);
    convert_x_kernel<<<(BSZ * DIM / 4) / 256, 256>>>(x);
    dim3 gg(BSZ / GBM, SS / GBN);   // (2, 256); m fast -> L2 sharing of weight rows
    fused_gemm_kernel<<<gg, 256, DSMEM>>>(weight, bias, sid, targets, san);
    loss_kernel<<<BSZ, 256>>>((float*)d_out);
}